// round 4
// baseline (speedup 1.0000x reference)
#include <cuda_runtime.h>
#include <math.h>
#include <stdint.h>

#define T 1024
#define H 1024
#define FF 2048
#define E 8
#define KSEL 2
#define NSLOT (T * KSEL)   // 2048
#define NK1 (H / 32)       // 32 k-chunks in gemm1
#define NK2 (FF / 32)      // 64 k-chunks in gemm2

// ---------------- scratch (device globals: allocation-free) ----------------
__device__ int   g_count[E];
__device__ int   g_offset[E];
__device__ int   g_tok[NSLOT];
__device__ float g_scale[NSLOT];
__device__ float g_act[(size_t)NSLOT * FF];                 // fp32 act scratch (16.8MB)
__device__ unsigned char g_hq[(size_t)T * H * 2];           // 2MB
__device__ unsigned char g_w1q[(size_t)E * 2 * FF * H * 2]; // 67MB
__device__ unsigned char g_w2q[(size_t)E * H * FF * 2];     // 33.5MB
__device__ unsigned char g_actq[(size_t)NSLOT * FF * 2];    // 8MB
__device__ float g_sh[T];
__device__ float g_sw1[E * 2 * FF];
__device__ float g_sw2[E * H];
__device__ float g_sact[NSLOT];

// ---------------- helpers ----------------
__device__ __forceinline__ uint32_t s2u(const void* p) {
    return (uint32_t)__cvta_generic_to_shared(p);
}
__device__ __forceinline__ void ldsm4(uint32_t (&r)[4], uint32_t addr) {
    asm volatile("ldmatrix.sync.aligned.m8n8.x4.shared.b16 {%0,%1,%2,%3}, [%4];"
                 : "=r"(r[0]), "=r"(r[1]), "=r"(r[2]), "=r"(r[3]) : "r"(addr));
}
__device__ __forceinline__ void ldsm2(uint32_t (&r)[2], uint32_t addr) {
    asm volatile("ldmatrix.sync.aligned.m8n8.x2.shared.b16 {%0,%1}, [%2];"
                 : "=r"(r[0]), "=r"(r[1]) : "r"(addr));
}
__device__ __forceinline__ void mma_s8(int (&c)[4], const uint32_t (&a)[4],
                                       const uint32_t (&b)[2]) {
    asm volatile(
        "mma.sync.aligned.m16n8k32.row.col.s32.s8.s8.s32 "
        "{%0,%1,%2,%3},{%4,%5,%6,%7},{%8,%9},{%0,%1,%2,%3};"
        : "+r"(c[0]), "+r"(c[1]), "+r"(c[2]), "+r"(c[3])
        : "r"(a[0]), "r"(a[1]), "r"(a[2]), "r"(a[3]), "r"(b[0]), "r"(b[1]));
}
__device__ __forceinline__ void cpa16(uint32_t dst, const void* src) {
    asm volatile("cp.async.cg.shared.global [%0], [%1], 16;" :: "r"(dst), "l"(src));
}
#define CP_COMMIT() asm volatile("cp.async.commit_group;" ::: "memory")
#define CP_WAIT1()  asm volatile("cp.async.wait_group 1;" ::: "memory")
#define CP_WAIT0()  asm volatile("cp.async.wait_group 0;" ::: "memory")

// quantize one float -> (hi, lo) int8 contributing i = 256*hi + lo, |i| <= 32639
__device__ __forceinline__ void q15(float x, float inv, int& h, int& l) {
    int i = __float2int_rn(x * inv);
    i = max(-32639, min(32639, i));
    h = (i + 128) >> 8;
    l = i - (h << 8);
}
__device__ __forceinline__ uint32_t pack4(int b0, int b1, int b2, int b3) {
    return (uint32_t)(b0 & 0xff) | ((uint32_t)(b1 & 0xff) << 8) |
           ((uint32_t)(b2 & 0xff) << 16) | ((uint32_t)b3 << 24);
}

#define LDS_ROW 80   // 64B data (hi32|lo32) + 16B pad: conflict-free ldmatrix

// ---------------- routing ----------------
__global__ void route_kernel(const int* __restrict__ sel,
                             const float* __restrict__ scales) {
    __shared__ int s_cnt[E], s_off[E], s_cur[E];
    int tid = threadIdx.x;
    if (tid < E) { s_cnt[tid] = 0; s_cur[tid] = 0; }
    __syncthreads();
    for (int i = tid; i < NSLOT; i += blockDim.x)
        atomicAdd(&s_cnt[sel[i]], 1);
    __syncthreads();
    if (tid == 0) {
        int acc = 0;
        for (int e = 0; e < E; e++) { s_off[e] = acc; acc += s_cnt[e]; }
    }
    __syncthreads();
    if (tid < E) { g_count[tid] = s_cnt[tid]; g_offset[tid] = s_off[tid]; }
    for (int i = tid; i < NSLOT; i += blockDim.x) {
        int e = sel[i];
        int pos = s_off[e] + atomicAdd(&s_cur[e], 1);
        g_tok[pos]   = i / KSEL;
        g_scale[pos] = scales[i];
    }
}

// ---------------- fused rowmax + 15-bit quantize --------------------------
// one block per row; dst layout: [row][k/32][hi 32B | lo 32B]
__global__ void quant_rows(const float* __restrict__ src,
                           unsigned char* __restrict__ dst,
                           float* __restrict__ scales, int R) {
    const int row = blockIdx.x, tid = threadIdx.x;
    const int lane = tid & 31, wid = tid >> 5;
    const float* s = src + (size_t)row * R;
    float4 v[2];
    float m = 0.0f;
    const int nv = R >> 10;    // 1 or 2
    for (int jj = 0; jj < nv; jj++) {
        v[jj] = *(const float4*)(s + jj * 1024 + tid * 4);
        m = fmaxf(m, fmaxf(fmaxf(fabsf(v[jj].x), fabsf(v[jj].y)),
                           fmaxf(fabsf(v[jj].z), fabsf(v[jj].w))));
    }
#pragma unroll
    for (int o = 16; o > 0; o >>= 1)
        m = fmaxf(m, __shfl_xor_sync(0xffffffffu, m, o));
    __shared__ float sm8[8];
    __shared__ float s_inv;
    if (lane == 0) sm8[wid] = m;
    __syncthreads();
    if (tid == 0) {
        float mm = 0.0f;
        for (int i = 0; i < 8; i++) mm = fmaxf(mm, sm8[i]);
        scales[row] = mm / 32639.0f;
        s_inv = (mm > 0.0f) ? 32639.0f / mm : 0.0f;
    }
    __syncthreads();
    const float inv = s_inv;
    unsigned char* d = dst + (size_t)row * (R * 2);
    for (int jj = 0; jj < nv; jj++) {
        const int k0 = jj * 1024 + tid * 4;
        int h0, l0, h1, l1, h2, l2, h3, l3;
        q15(v[jj].x, inv, h0, l0);
        q15(v[jj].y, inv, h1, l1);
        q15(v[jj].z, inv, h2, l2);
        q15(v[jj].w, inv, h3, l3);
        const int chunk = k0 >> 5, off = k0 & 31;
        *(uint32_t*)(d + chunk * 64 + off)      = pack4(h0, h1, h2, h3);
        *(uint32_t*)(d + chunk * 64 + 32 + off) = pack4(l0, l1, l2, l3);
    }
}

// ---------------- GEMM1: act = silu(X*W1g+b) * (X*W1l+b) -------------------
// CTA: M=128, Ngate=64, Nlin=64. smem tiles: A 128 rows, B 128 rows (64g+64l).
#define G1_B   (128 * LDS_ROW)          // B region offset (10240)
#define G1_BUF (256 * LDS_ROW)          // 20480 per stage

__global__ __launch_bounds__(256, 1)
void gemm1_kernel(const float* __restrict__ b1) {
    const int e   = blockIdx.y;
    const int cnt = g_count[e];
    const int m0  = blockIdx.z * 128;
    if (m0 >= cnt) return;
    const int n0  = blockIdx.x * 64;
    const int off = g_offset[e];

    extern __shared__ char sm[];
    __shared__ float s_bg[64], s_bl[64], s_sg[64], s_sl[64];

    const int tid = threadIdx.x, lane = tid & 31, wid = tid >> 5;
    const int wm = wid & 1, wn = wid >> 1;

    if (tid < 64) {
        s_bg[tid] = b1[(size_t)e * 2 * FF + n0 + tid];
        s_sg[tid] = g_sw1[e * 2 * FF + n0 + tid];
    } else if (tid < 128) {
        const int c = tid - 64;
        s_bl[c] = b1[(size_t)e * 2 * FF + FF + n0 + c];
        s_sl[c] = g_sw1[e * 2 * FF + FF + n0 + c];
    }

    // cp.async mapping: thread owns one row's 32B half (2x 16B) for A and B
    const int crow = tid >> 1;
    const int cp0  = (tid & 1) * 32;
    const int mrow = m0 + crow;
    const int slot = off + (mrow < cnt ? mrow : cnt - 1);
    const unsigned char* srcA = g_hq + (size_t)g_tok[slot] * (H * 2) + cp0;
    const unsigned char* srcB =
        (crow < 64)
            ? g_w1q + (size_t)(e * 2 * FF + n0 + crow) * (H * 2) + cp0
            : g_w1q + (size_t)(e * 2 * FF + FF + n0 + (crow - 64)) * (H * 2) + cp0;
    const uint32_t smb = s2u(sm);
    const uint32_t dA = smb + crow * LDS_ROW + cp0;
    const uint32_t dB = smb + G1_B + crow * LDS_ROW + cp0;

    // ldmatrix bases
    const int rowA = wm * 64 + (lane & 7) + ((lane >> 3) & 1) * 8;
    const uint32_t laA = (uint32_t)rowA * LDS_ROW + (lane >> 4) * 16;
    const uint32_t lbB = (uint32_t)(wn * 16 + (lane & 7)) * LDS_ROW +
                         ((lane >> 3) & 1) * 16 + G1_B;

    int ghh[4][2][4] = {}, gcr[4][2][4] = {}, lhh[4][2][4] = {}, lcr[4][2][4] = {};

    // prologue: issue chunk 0
    cpa16(dA, srcA);      cpa16(dA + 16, srcA + 16);
    cpa16(dB, srcB);      cpa16(dB + 16, srcB + 16);
    CP_COMMIT();

    for (int kt = 0; kt < NK1; kt++) {
        if (kt + 1 < NK1) {
            const uint32_t db = ((kt + 1) & 1) * G1_BUF;
            const unsigned char* sa = srcA + (kt + 1) * 64;
            const unsigned char* sb = srcB + (kt + 1) * 64;
            cpa16(dA + db, sa);      cpa16(dA + db + 16, sa + 16);
            cpa16(dB + db, sb);      cpa16(dB + db + 16, sb + 16);
            CP_COMMIT();
            CP_WAIT1();
        } else {
            CP_WAIT0();
        }
        __syncthreads();

        const uint32_t bb = smb + (kt & 1) * G1_BUF;
        uint32_t ah[4][4], al[4][4];
#pragma unroll
        for (int i = 0; i < 4; i++) {
            ldsm4(ah[i], bb + laA + i * (16 * LDS_ROW));
            ldsm4(al[i], bb + laA + i * (16 * LDS_ROW) + 32);
        }
#pragma unroll
        for (int j = 0; j < 2; j++) {
            const uint32_t ba = bb + lbB + j * (8 * LDS_ROW);
            uint32_t bgh[2], bgl[2], blh[2], bll[2];
            ldsm2(bgh, ba);
            ldsm2(bgl, ba + 32);
            ldsm2(blh, ba + 64 * LDS_ROW);
            ldsm2(bll, ba + 64 * LDS_ROW + 32);
#pragma unroll
            for (int i = 0; i < 4; i++) {
                mma_s8(ghh[i][j], ah[i], bgh);
                mma_s8(gcr[i][j], ah[i], bgl);
                mma_s8(gcr[i][j], al[i], bgh);
                mma_s8(lhh[i][j], ah[i], blh);
                mma_s8(lcr[i][j], ah[i], bll);
                mma_s8(lcr[i][j], al[i], blh);
            }
        }
        __syncthreads();
    }

    // epilogue: v = sa*sb*(65536*HH + 256*CR); gate->silu * lin; fp32 store
#pragma unroll
    for (int i = 0; i < 4; i++)
#pragma unroll
        for (int rr = 0; rr < 2; rr++) {
            const int m = wm * 64 + i * 16 + (lane >> 2) + rr * 8 + m0;
            if (m >= cnt) continue;
            const int   sl = off + m;
            const float sa256 = g_sh[g_tok[sl]] * 256.0f;
#pragma unroll
            for (int j = 0; j < 2; j++) {
                const int c = wn * 16 + j * 8 + (lane & 3) * 2;
                float2 o;
#pragma unroll
                for (int q = 0; q < 2; q++) {
                    const int idx = rr * 2 + q;
                    const float fg = fmaf(256.0f, (float)ghh[i][j][idx],
                                          (float)gcr[i][j][idx]);
                    const float fl = fmaf(256.0f, (float)lhh[i][j][idx],
                                          (float)lcr[i][j][idx]);
                    const float g = fg * (sa256 * s_sg[c + q]) + s_bg[c + q];
                    const float l = fl * (sa256 * s_sl[c + q]) + s_bl[c + q];
                    const float r = g * l / (1.0f + __expf(-g));
                    if (q == 0) o.x = r; else o.y = r;
                }
                *(float2*)&g_act[(size_t)sl * FF + n0 + c] = o;
            }
        }
}

// ---------------- GEMM2: out += scale*(act*W2^T + b2) ----------------------
// CTA: M=128, N=64 over H, K=FF. Includes LL product (K=2048 accuracy).
#define G2_B   (128 * LDS_ROW)
#define G2_BUF (192 * LDS_ROW)   // A 128 rows + B 64 rows = 15360 per stage

__global__ __launch_bounds__(256, 1)
void gemm2_kernel(const float* __restrict__ b2, float* __restrict__ out) {
    const int e   = blockIdx.y;
    const int cnt = g_count[e];
    const int m0  = blockIdx.z * 128;
    if (m0 >= cnt) return;
    const int n0  = blockIdx.x * 64;
    const int off = g_offset[e];

    extern __shared__ char sm[];
    __shared__ float s_b2[64], s_sb[64];

    const int tid = threadIdx.x, lane = tid & 31, wid = tid >> 5;
    const int wm = wid & 1, wn = wid >> 1;

    if (tid < 64) {
        s_b2[tid] = b2[(size_t)e * H + n0 + tid];
        s_sb[tid] = g_sw2[e * H + n0 + tid];
    }

    // cp.async mapping: A rows (2x16B per thread), B rows (1x16B per thread)
    const int arow = tid >> 1;
    const int acp0 = (tid & 1) * 32;
    const int mrow = m0 + arow;
    const unsigned char* srcA =
        g_actq + (size_t)(off + (mrow < cnt ? mrow : cnt - 1)) * (FF * 2) + acp0;
    const int brow = tid >> 2;
    const int bcp0 = (tid & 3) * 16;
    const unsigned char* srcB = g_w2q + (size_t)(e * H + n0 + brow) * (FF * 2) + bcp0;

    const uint32_t smb = s2u(sm);
    const uint32_t dA = smb + arow * LDS_ROW + acp0;
    const uint32_t dB = smb + G2_B + brow * LDS_ROW + bcp0;

    const int rowA = wm * 64 + (lane & 7) + ((lane >> 3) & 1) * 8;
    const uint32_t laA = (uint32_t)rowA * LDS_ROW + (lane >> 4) * 16;
    const uint32_t lbB = (uint32_t)(wn * 16 + (lane & 7)) * LDS_ROW +
                         ((lane >> 3) & 1) * 16 + G2_B;

    int chh[4][2][4] = {}, ccr[4][2][4] = {}, cll[4][2][4] = {};

    cpa16(dA, srcA);  cpa16(dA + 16, srcA + 16);
    cpa16(dB, srcB);
    CP_COMMIT();

    for (int kt = 0; kt < NK2; kt++) {
        if (kt + 1 < NK2) {
            const uint32_t db = ((kt + 1) & 1) * G2_BUF;
            const unsigned char* sa = srcA + (kt + 1) * 64;
            const unsigned char* sb = srcB + (kt + 1) * 64;
            cpa16(dA + db, sa);  cpa16(dA + db + 16, sa + 16);
            cpa16(dB + db, sb);
            CP_COMMIT();
            CP_WAIT1();
        } else {
            CP_WAIT0();
        }
        __syncthreads();

        const uint32_t bb = smb + (kt & 1) * G2_BUF;
        uint32_t ah[4][4], al[4][4];
#pragma unroll
        for (int i = 0; i < 4; i++) {
            ldsm4(ah[i], bb + laA + i * (16 * LDS_ROW));
            ldsm4(al[i], bb + laA + i * (16 * LDS_ROW) + 32);
        }
#pragma unroll
        for (int j = 0; j < 2; j++) {
            const uint32_t ba = bb + lbB + j * (8 * LDS_ROW);
            uint32_t bh[2], bl[2];
            ldsm2(bh, ba);
            ldsm2(bl, ba + 32);
#pragma unroll
            for (int i = 0; i < 4; i++) {
                mma_s8(chh[i][j], ah[i], bh);
                mma_s8(ccr[i][j], ah[i], bl);
                mma_s8(ccr[i][j], al[i], bh);
                mma_s8(cll[i][j], al[i], bl);
            }
        }
        __syncthreads();
    }

    // epilogue: v = sa*sb*(65536*HH + 256*CR + LL); atomic scatter-add
#pragma unroll
    for (int i = 0; i < 4; i++)
#pragma unroll
        for (int rr = 0; rr < 2; rr++) {
            const int m = wm * 64 + i * 16 + (lane >> 2) + rr * 8 + m0;
            if (m >= cnt) continue;
            const int   sl  = off + m;
            const int   tok = g_tok[sl];
            const float sc  = g_scale[sl];
            const float sa  = g_sact[sl];
#pragma unroll
            for (int j = 0; j < 2; j++) {
                const int c = wn * 16 + j * 8 + (lane & 3) * 2;
#pragma unroll
                for (int q = 0; q < 2; q++) {
                    const int idx = rr * 2 + q;
                    const float f = fmaf(256.0f,
                                         fmaf(256.0f, (float)chh[i][j][idx],
                                              (float)ccr[i][j][idx]),
                                         (float)cll[i][j][idx]);
                    const float v = f * (sa * s_sb[c + q]) + s_b2[c + q];
                    atomicAdd(&out[(size_t)tok * H + n0 + c + q], sc * v);
                }
            }
        }
}

// ---------------- launch ----------------
extern "C" void kernel_launch(void* const* d_in, const int* in_sizes, int n_in,
                              void* d_out, int out_size) {
    const float* hidden = (const float*)d_in[0];
    const int*   sel    = (const int*)d_in[1];
    const float* scales = (const float*)d_in[2];
    const float* w1     = (const float*)d_in[3];
    const float* b1     = (const float*)d_in[4];
    const float* w2     = (const float*)d_in[5];
    const float* b2     = (const float*)d_in[6];

    // device-global symbol addresses (host API, no allocation)
    void *p_hq, *p_w1q, *p_w2q, *p_actq, *p_act, *p_sh, *p_sw1, *p_sw2, *p_sact;
    cudaGetSymbolAddress(&p_hq,   g_hq);
    cudaGetSymbolAddress(&p_w1q,  g_w1q);
    cudaGetSymbolAddress(&p_w2q,  g_w2q);
    cudaGetSymbolAddress(&p_actq, g_actq);
    cudaGetSymbolAddress(&p_act,  g_act);
    cudaGetSymbolAddress(&p_sh,   g_sh);
    cudaGetSymbolAddress(&p_sw1,  g_sw1);
    cudaGetSymbolAddress(&p_sw2,  g_sw2);
    cudaGetSymbolAddress(&p_sact, g_sact);

    const int smem1 = 2 * G1_BUF;   // 40960
    const int smem2 = 2 * G2_BUF;   // 30720
    cudaFuncSetAttribute(gemm1_kernel, cudaFuncAttributeMaxDynamicSharedMemorySize, smem1);
    cudaFuncSetAttribute(gemm2_kernel, cudaFuncAttributeMaxDynamicSharedMemorySize, smem2);

    cudaMemsetAsync(d_out, 0, (size_t)T * H * sizeof(float), 0);
    route_kernel<<<1, 256>>>(sel, scales);

    quant_rows<<<T, 256>>>(hidden, (unsigned char*)p_hq, (float*)p_sh, H);
    quant_rows<<<E * 2 * FF, 256>>>(w1, (unsigned char*)p_w1q, (float*)p_sw1, H);
    quant_rows<<<E * H, 256>>>(w2, (unsigned char*)p_w2q, (float*)p_sw2, FF);

    dim3 g1(FF / 64, E, NSLOT / 128);   // 32 x 8 x 16
    gemm1_kernel<<<g1, 256, smem1>>>(b1);

    quant_rows<<<NSLOT, 256>>>((const float*)p_act, (unsigned char*)p_actq,
                               (float*)p_sact, FF);

    dim3 g2(H / 64, E, NSLOT / 128);    // 16 x 8 x 16
    gemm2_kernel<<<g2, 256, smem2>>>(b2, (float*)d_out);
}

// round 5
// speedup vs baseline: 1.5714x; 1.5714x over previous
#include <cuda_runtime.h>
#include <cuda_bf16.h>
#include <math.h>
#include <stdint.h>

#define T 1024
#define H 1024
#define FF 2048
#define E 8
#define KSEL 2
#define NSLOT (T * KSEL)   // 2048
#define NK1 (H / 32)       // 32 k-chunks gemm1
#define NK2 (FF / 32)      // 64 k-chunks gemm2

// ---------------- scratch (device globals: allocation-free) ----------------
__device__ int   g_count[E];
__device__ int   g_offset[E];
__device__ int   g_tok[NSLOT];
__device__ float g_scale[NSLOT];
// packed split-bf16 layout: per 32-value chunk: 64B hi | 64B lo (128B = 4B/val)
__device__ unsigned char g_hs[(size_t)T * H * 4];            // 4MB
__device__ unsigned char g_w1s[(size_t)E * 2 * FF * H * 4];  // 134MB
__device__ unsigned char g_w2s[(size_t)E * H * FF * 4];      // 67MB
__device__ unsigned char g_acts[(size_t)NSLOT * FF * 4];     // 16MB

// ---------------- helpers ----------------
__device__ __forceinline__ uint32_t s2u(const void* p) {
    return (uint32_t)__cvta_generic_to_shared(p);
}
__device__ __forceinline__ void ldsm4(uint32_t (&r)[4], uint32_t addr) {
    asm volatile("ldmatrix.sync.aligned.m8n8.x4.shared.b16 {%0,%1,%2,%3}, [%4];"
                 : "=r"(r[0]), "=r"(r[1]), "=r"(r[2]), "=r"(r[3]) : "r"(addr));
}
__device__ __forceinline__ void ldsm2(uint32_t (&r)[2], uint32_t addr) {
    asm volatile("ldmatrix.sync.aligned.m8n8.x2.shared.b16 {%0,%1}, [%2];"
                 : "=r"(r[0]), "=r"(r[1]) : "r"(addr));
}
__device__ __forceinline__ void mma16816(float (&c)[4], const uint32_t (&a)[4],
                                         const uint32_t (&b)[2]) {
    asm volatile(
        "mma.sync.aligned.m16n8k16.row.col.f32.bf16.bf16.f32 "
        "{%0,%1,%2,%3},{%4,%5,%6,%7},{%8,%9},{%0,%1,%2,%3};"
        : "+f"(c[0]), "+f"(c[1]), "+f"(c[2]), "+f"(c[3])
        : "r"(a[0]), "r"(a[1]), "r"(a[2]), "r"(a[3]), "r"(b[0]), "r"(b[1]));
}
__device__ __forceinline__ void cpa16(uint32_t dst, const void* src) {
    asm volatile("cp.async.cg.shared.global [%0], [%1], 16;" :: "r"(dst), "l"(src));
}
#define CP_COMMIT() asm volatile("cp.async.commit_group;" ::: "memory")
#define CP_WAIT1()  asm volatile("cp.async.wait_group 1;" ::: "memory")
#define CP_WAIT0()  asm volatile("cp.async.wait_group 0;" ::: "memory")

__device__ __forceinline__ uint32_t pack_bf2(__nv_bfloat16 a, __nv_bfloat16 b) {
    return (uint32_t)__bfloat16_as_ushort(a) | ((uint32_t)__bfloat16_as_ushort(b) << 16);
}
// split 2 floats -> hi pair + lo pair
__device__ __forceinline__ void split2(float x0, float x1, uint32_t& h, uint32_t& l) {
    __nv_bfloat16 h0 = __float2bfloat16(x0);
    __nv_bfloat16 h1 = __float2bfloat16(x1);
    __nv_bfloat16 l0 = __float2bfloat16(x0 - __bfloat162float(h0));
    __nv_bfloat16 l1 = __float2bfloat16(x1 - __bfloat162float(h1));
    h = pack_bf2(h0, h1);
    l = pack_bf2(l0, l1);
}

#define LDS_ROW 144   // 128B data (hi64|lo64) + 16B pad: conflict-free ldmatrix

// ---------------- routing ----------------
__global__ void route_kernel(const int* __restrict__ sel,
                             const float* __restrict__ scales) {
    __shared__ int s_cnt[E], s_off[E], s_cur[E];
    int tid = threadIdx.x;
    if (tid < E) { s_cnt[tid] = 0; s_cur[tid] = 0; }
    __syncthreads();
    for (int i = tid; i < NSLOT; i += blockDim.x)
        atomicAdd(&s_cnt[sel[i]], 1);
    __syncthreads();
    if (tid == 0) {
        int acc = 0;
        for (int e = 0; e < E; e++) { s_off[e] = acc; acc += s_cnt[e]; }
    }
    __syncthreads();
    if (tid < E) { g_count[tid] = s_cnt[tid]; g_offset[tid] = s_off[tid]; }
    for (int i = tid; i < NSLOT; i += blockDim.x) {
        int e = sel[i];
        int pos = s_off[e] + atomicAdd(&s_cur[e], 1);
        g_tok[pos]   = i / KSEL;
        g_scale[pos] = scales[i];
    }
}

// ---------------- pre-split fp32 -> packed bf16 hi/lo ----------------------
// dst element i: chunk (i>>5) at 128B; hi at (i&31)*2, lo at +64.
__global__ void split_rows(const float* __restrict__ src,
                           unsigned char* __restrict__ dst, int total4) {
    int i4 = blockIdx.x * blockDim.x + threadIdx.x;
    if (i4 >= total4) return;
    const int i = i4 * 4;
    float4 v = ((const float4*)src)[i4];
    uint32_t h0, l0, h1, l1;
    split2(v.x, v.y, h0, l0);
    split2(v.z, v.w, h1, l1);
    unsigned char* base = dst + (size_t)(i >> 5) * 128 + (i & 31) * 2;
    *(uint2*)base        = make_uint2(h0, h1);
    *(uint2*)(base + 64) = make_uint2(l0, l1);
}

// ---------------- GEMM1: act = silu(X*W1g+b) * (X*W1l+b) -------------------
// CTA: M=128, Ngate=64, Nlin=64, k-chunk=32. 3-product bf16 (hh, hl, lh).
#define G1_B   (128 * LDS_ROW)   // 18432
#define G1_BUF (256 * LDS_ROW)   // 36864 per stage

__global__ __launch_bounds__(256, 1)
void gemm1_kernel(const float* __restrict__ b1) {
    const int e   = blockIdx.y;
    const int cnt = g_count[e];
    const int m0  = blockIdx.z * 128;
    if (m0 >= cnt) return;
    const int n0  = blockIdx.x * 64;
    const int off = g_offset[e];

    extern __shared__ char sm[];
    __shared__ float s_bg[64], s_bl[64];

    const int tid = threadIdx.x, lane = tid & 31, wid = tid >> 5;
    const int wm = wid & 1, wn = wid >> 1;

    if (tid < 64)       s_bg[tid]      = b1[(size_t)e * 2 * FF + n0 + tid];
    else if (tid < 128) s_bl[tid - 64] = b1[(size_t)e * 2 * FF + FF + n0 + tid - 64];

    // cp.async mapping: thread owns 64B (4x16B) of one row for A and for B
    const int crow = tid >> 1;
    const int cp0  = (tid & 1) * 64;
    const int mrow = m0 + crow;
    const int slot = off + (mrow < cnt ? mrow : cnt - 1);
    const unsigned char* srcA = g_hs + (size_t)g_tok[slot] * (H * 4) + cp0;
    const unsigned char* srcB =
        (crow < 64)
            ? g_w1s + (size_t)(e * 2 * FF + n0 + crow) * (H * 4) + cp0
            : g_w1s + (size_t)(e * 2 * FF + FF + n0 + (crow - 64)) * (H * 4) + cp0;
    const uint32_t smb = s2u(sm);
    const uint32_t dA = smb + crow * LDS_ROW + cp0;
    const uint32_t dB = smb + G1_B + crow * LDS_ROW + cp0;

    // ldmatrix bases (R3-verified mapping; hi at +0/+32 for kk, lo at +64)
    const uint32_t laA = (uint32_t)((lane & 15) + wm * 64) * LDS_ROW + (lane >> 4) * 16;
    const uint32_t lbB = (uint32_t)(wn * 16 + (lane & 7)) * LDS_ROW +
                         ((lane >> 3) & 1) * 16 + G1_B;

    float cg[4][2][4] = {}, cl[4][2][4] = {};

    // prologue: stage 0
#pragma unroll
    for (int q = 0; q < 4; q++) { cpa16(dA + q * 16, srcA + q * 16); }
#pragma unroll
    for (int q = 0; q < 4; q++) { cpa16(dB + q * 16, srcB + q * 16); }
    CP_COMMIT();

    for (int kt = 0; kt < NK1; kt++) {
        if (kt + 1 < NK1) {
            const uint32_t db = ((kt + 1) & 1) * G1_BUF;
            const unsigned char* sa = srcA + (kt + 1) * 128;
            const unsigned char* sb = srcB + (kt + 1) * 128;
#pragma unroll
            for (int q = 0; q < 4; q++) { cpa16(dA + db + q * 16, sa + q * 16); }
#pragma unroll
            for (int q = 0; q < 4; q++) { cpa16(dB + db + q * 16, sb + q * 16); }
            CP_COMMIT();
            CP_WAIT1();
        } else {
            CP_WAIT0();
        }
        __syncthreads();

        const uint32_t bb = smb + (kt & 1) * G1_BUF;
#pragma unroll
        for (int kk = 0; kk < 2; kk++) {
            uint32_t ah[4][4], al[4][4];
#pragma unroll
            for (int i = 0; i < 4; i++) {
                const uint32_t a0 = bb + laA + i * (16 * LDS_ROW) + kk * 32;
                ldsm4(ah[i], a0);
                ldsm4(al[i], a0 + 64);
            }
#pragma unroll
            for (int j = 0; j < 2; j++) {
                const uint32_t ba = bb + lbB + j * (8 * LDS_ROW) + kk * 32;
                uint32_t bgh[2], bgl[2], blh[2], bll[2];
                ldsm2(bgh, ba);
                ldsm2(bgl, ba + 64);
                ldsm2(blh, ba + 64 * LDS_ROW);
                ldsm2(bll, ba + 64 * LDS_ROW + 64);
#pragma unroll
                for (int i = 0; i < 4; i++) {
                    mma16816(cg[i][j], ah[i], bgh);
                    mma16816(cg[i][j], ah[i], bgl);
                    mma16816(cg[i][j], al[i], bgh);
                    mma16816(cl[i][j], ah[i], blh);
                    mma16816(cl[i][j], ah[i], bll);
                    mma16816(cl[i][j], al[i], blh);
                }
            }
        }
        __syncthreads();
    }

    // epilogue: bias + silu(gate)*lin, store act as split bf16 (gemm2 layout)
#pragma unroll
    for (int i = 0; i < 4; i++)
#pragma unroll
        for (int rr = 0; rr < 2; rr++) {
            const int m = wm * 64 + i * 16 + (lane >> 2) + rr * 8 + m0;
            if (m >= cnt) continue;
            unsigned char* arow = g_acts + (size_t)(off + m) * (FF * 4);
#pragma unroll
            for (int j = 0; j < 2; j++) {
                const int c = wn * 16 + j * 8 + (lane & 3) * 2;
                float r0, r1;
#pragma unroll
                for (int q = 0; q < 2; q++) {
                    const int idx = rr * 2 + q;
                    const float g = cg[i][j][idx] + s_bg[c + q];
                    const float l = cl[i][j][idx] + s_bl[c + q];
                    const float r = g * l / (1.0f + __expf(-g));
                    if (q == 0) r0 = r; else r1 = r;
                }
                uint32_t h, lo;
                split2(r0, r1, h, lo);
                const int C = n0 + c;
                unsigned char* base = arow + (size_t)(C >> 5) * 128 + (C & 31) * 2;
                *(uint32_t*)base        = h;
                *(uint32_t*)(base + 64) = lo;
            }
        }
}

// ---------------- GEMM2: out += scale*(act*W2^T + b2) ----------------------
// CTA: M=128, N=64 over H, K=FF.
#define G2_B   (128 * LDS_ROW)
#define G2_BUF (192 * LDS_ROW)   // A 128 + B 64 rows = 27648 per stage

__global__ __launch_bounds__(256, 1)
void gemm2_kernel(const float* __restrict__ b2, float* __restrict__ out) {
    const int e   = blockIdx.y;
    const int cnt = g_count[e];
    const int m0  = blockIdx.z * 128;
    if (m0 >= cnt) return;
    const int n0  = blockIdx.x * 64;
    const int off = g_offset[e];

    extern __shared__ char sm[];
    __shared__ float s_b2[64];

    const int tid = threadIdx.x, lane = tid & 31, wid = tid >> 5;
    const int wm = wid & 1, wn = wid >> 1;

    if (tid < 64) s_b2[tid] = b2[(size_t)e * H + n0 + tid];

    const int arow = tid >> 1;
    const int acp0 = (tid & 1) * 64;
    const int mrow = m0 + arow;
    const unsigned char* srcA =
        g_acts + (size_t)(off + (mrow < cnt ? mrow : cnt - 1)) * (FF * 4) + acp0;
    const int brow = tid >> 2;
    const int bcp0 = (tid & 3) * 32;
    const unsigned char* srcB = g_w2s + (size_t)(e * H + n0 + brow) * (FF * 4) + bcp0;

    const uint32_t smb = s2u(sm);
    const uint32_t dA = smb + arow * LDS_ROW + acp0;
    const uint32_t dB = smb + G2_B + brow * LDS_ROW + bcp0;

    const uint32_t laA = (uint32_t)((lane & 15) + wm * 64) * LDS_ROW + (lane >> 4) * 16;
    const uint32_t lbB = (uint32_t)(wn * 16 + (lane & 7)) * LDS_ROW +
                         ((lane >> 3) & 1) * 16 + G2_B;

    float c[4][2][4] = {};

#pragma unroll
    for (int q = 0; q < 4; q++) { cpa16(dA + q * 16, srcA + q * 16); }
    cpa16(dB, srcB);  cpa16(dB + 16, srcB + 16);
    CP_COMMIT();

    for (int kt = 0; kt < NK2; kt++) {
        if (kt + 1 < NK2) {
            const uint32_t db = ((kt + 1) & 1) * G2_BUF;
            const unsigned char* sa = srcA + (kt + 1) * 128;
            const unsigned char* sb = srcB + (kt + 1) * 128;
#pragma unroll
            for (int q = 0; q < 4; q++) { cpa16(dA + db + q * 16, sa + q * 16); }
            cpa16(dB + db, sb);  cpa16(dB + db + 16, sb + 16);
            CP_COMMIT();
            CP_WAIT1();
        } else {
            CP_WAIT0();
        }
        __syncthreads();

        const uint32_t bb = smb + (kt & 1) * G2_BUF;
#pragma unroll
        for (int kk = 0; kk < 2; kk++) {
            uint32_t ah[4][4], al[4][4];
#pragma unroll
            for (int i = 0; i < 4; i++) {
                const uint32_t a0 = bb + laA + i * (16 * LDS_ROW) + kk * 32;
                ldsm4(ah[i], a0);
                ldsm4(al[i], a0 + 64);
            }
#pragma unroll
            for (int j = 0; j < 2; j++) {
                const uint32_t ba = bb + lbB + j * (8 * LDS_ROW) + kk * 32;
                uint32_t bh[2], bl[2];
                ldsm2(bh, ba);
                ldsm2(bl, ba + 64);
#pragma unroll
                for (int i = 0; i < 4; i++) {
                    mma16816(c[i][j], ah[i], bh);
                    mma16816(c[i][j], ah[i], bl);
                    mma16816(c[i][j], al[i], bh);
                }
            }
        }
        __syncthreads();
    }

    // epilogue: scaled atomic scatter
#pragma unroll
    for (int i = 0; i < 4; i++)
#pragma unroll
        for (int rr = 0; rr < 2; rr++) {
            const int m = wm * 64 + i * 16 + (lane >> 2) + rr * 8 + m0;
            if (m >= cnt) continue;
            const int   sl  = off + m;
            const int   tok = g_tok[sl];
            const float sc  = g_scale[sl];
#pragma unroll
            for (int j = 0; j < 2; j++) {
                const int cc = wn * 16 + j * 8 + (lane & 3) * 2;
                atomicAdd(&out[(size_t)tok * H + n0 + cc],
                          sc * (c[i][j][rr * 2 + 0] + s_b2[cc]));
                atomicAdd(&out[(size_t)tok * H + n0 + cc + 1],
                          sc * (c[i][j][rr * 2 + 1] + s_b2[cc + 1]));
            }
        }
}

// ---------------- launch ----------------
extern "C" void kernel_launch(void* const* d_in, const int* in_sizes, int n_in,
                              void* d_out, int out_size) {
    const float* hidden = (const float*)d_in[0];
    const int*   sel    = (const int*)d_in[1];
    const float* scales = (const float*)d_in[2];
    const float* w1     = (const float*)d_in[3];
    const float* b1     = (const float*)d_in[4];
    const float* w2     = (const float*)d_in[5];
    const float* b2     = (const float*)d_in[6];

    void *p_hs, *p_w1s, *p_w2s;
    cudaGetSymbolAddress(&p_hs,  g_hs);
    cudaGetSymbolAddress(&p_w1s, g_w1s);
    cudaGetSymbolAddress(&p_w2s, g_w2s);

    const int smem1 = 2 * G1_BUF;   // 73728
    const int smem2 = 2 * G2_BUF;   // 55296
    cudaFuncSetAttribute(gemm1_kernel, cudaFuncAttributeMaxDynamicSharedMemorySize, smem1);
    cudaFuncSetAttribute(gemm2_kernel, cudaFuncAttributeMaxDynamicSharedMemorySize, smem2);

    cudaMemsetAsync(d_out, 0, (size_t)T * H * sizeof(float), 0);
    route_kernel<<<1, 256>>>(sel, scales);

    const int t4h  = (T * H) / 4;
    const int t4w1 = (E * 2 * FF * H) / 4;
    const int t4w2 = (E * H * FF) / 4;
    split_rows<<<(t4h  + 255) / 256, 256>>>(hidden, (unsigned char*)p_hs,  t4h);
    split_rows<<<(t4w1 + 255) / 256, 256>>>(w1,     (unsigned char*)p_w1s, t4w1);
    split_rows<<<(t4w2 + 255) / 256, 256>>>(w2,     (unsigned char*)p_w2s, t4w2);

    dim3 g1(FF / 64, E, NSLOT / 128);   // 32 x 8 x 16
    gemm1_kernel<<<g1, 256, smem1>>>(b1);

    dim3 g2(H / 64, E, NSLOT / 128);    // 16 x 8 x 16
    gemm2_kernel<<<g2, 256, smem2>>>(b2, (float*)d_out);
}

// round 6
// speedup vs baseline: 2.9808x; 1.8969x over previous
#include <cuda_runtime.h>
#include <cuda_fp16.h>
#include <math.h>
#include <stdint.h>

#define T 1024
#define H 1024
#define FF 2048
#define E 8
#define KSEL 2
#define NSLOT (T * KSEL)   // 2048
#define NK1 (H / 32)       // 32 k-chunks gemm1
#define NK2 (FF / 32)      // 64 k-chunks gemm2

// ---------------- scratch (device globals: allocation-free) ----------------
__device__ int   g_count[E];
__device__ int   g_offset[E];
__device__ int   g_tok[NSLOT];
__device__ float g_scale[NSLOT];
// split-fp16 chunk layout (A-side): per 32-value chunk: 64B hi | 64B lo
__device__ unsigned char g_hs[(size_t)T * H * 4];           // 4MB
__device__ unsigned char g_acts[(size_t)NSLOT * FF * 4];    // 16MB
// plain fp16 (B-side weights)
__device__ __half g_w1h[(size_t)E * 2 * FF * H];            // 67MB
__device__ __half g_w2h[(size_t)E * H * FF];                // 33.5MB

// ---------------- helpers ----------------
__device__ __forceinline__ uint32_t s2u(const void* p) {
    return (uint32_t)__cvta_generic_to_shared(p);
}
__device__ __forceinline__ void ldsm4(uint32_t (&r)[4], uint32_t addr) {
    asm volatile("ldmatrix.sync.aligned.m8n8.x4.shared.b16 {%0,%1,%2,%3}, [%4];"
                 : "=r"(r[0]), "=r"(r[1]), "=r"(r[2]), "=r"(r[3]) : "r"(addr));
}
__device__ __forceinline__ void ldsm2(uint32_t (&r)[2], uint32_t addr) {
    asm volatile("ldmatrix.sync.aligned.m8n8.x2.shared.b16 {%0,%1}, [%2];"
                 : "=r"(r[0]), "=r"(r[1]) : "r"(addr));
}
__device__ __forceinline__ void mma16816(float (&c)[4], const uint32_t (&a)[4],
                                         const uint32_t (&b)[2]) {
    asm volatile(
        "mma.sync.aligned.m16n8k16.row.col.f32.f16.f16.f32 "
        "{%0,%1,%2,%3},{%4,%5,%6,%7},{%8,%9},{%0,%1,%2,%3};"
        : "+f"(c[0]), "+f"(c[1]), "+f"(c[2]), "+f"(c[3])
        : "r"(a[0]), "r"(a[1]), "r"(a[2]), "r"(a[3]), "r"(b[0]), "r"(b[1]));
}
// split 2 floats -> hi fp16 pair + lo (residual) fp16 pair
__device__ __forceinline__ void split2h(float x0, float x1, uint32_t& h, uint32_t& l) {
    __half h0 = __float2half_rn(x0);
    __half h1 = __float2half_rn(x1);
    __half l0 = __float2half_rn(x0 - __half2float(h0));
    __half l1 = __float2half_rn(x1 - __half2float(h1));
    h = (uint32_t)__half_as_ushort(h0) | ((uint32_t)__half_as_ushort(h1) << 16);
    l = (uint32_t)__half_as_ushort(l0) | ((uint32_t)__half_as_ushort(l1) << 16);
}

#define ROW_A 144   // 128B data (hi64|lo64) + 16B pad
#define ROW_B 80    // 64B data + 16B pad

// ---------------- routing ----------------
__global__ void route_kernel(const int* __restrict__ sel,
                             const float* __restrict__ scales) {
    __shared__ int s_cnt[E], s_off[E], s_cur[E];
    int tid = threadIdx.x;
    if (tid < E) { s_cnt[tid] = 0; s_cur[tid] = 0; }
    __syncthreads();
    for (int i = tid; i < NSLOT; i += blockDim.x)
        atomicAdd(&s_cnt[sel[i]], 1);
    __syncthreads();
    if (tid == 0) {
        int acc = 0;
        for (int e = 0; e < E; e++) { s_off[e] = acc; acc += s_cnt[e]; }
    }
    __syncthreads();
    if (tid < E) { g_count[tid] = s_cnt[tid]; g_offset[tid] = s_off[tid]; }
    for (int i = tid; i < NSLOT; i += blockDim.x) {
        int e = sel[i];
        int pos = s_off[e] + atomicAdd(&s_cur[e], 1);
        g_tok[pos]   = i / KSEL;
        g_scale[pos] = scales[i];
    }
}

// ---------------- prep: fp32 -> plain fp16 ---------------------------------
__global__ void tofp16(const float* __restrict__ src, __half* __restrict__ dst,
                       int n4) {
    int i4 = blockIdx.x * blockDim.x + threadIdx.x;
    if (i4 >= n4) return;
    float4 v = ((const float4*)src)[i4];
    __half2 a = __floats2half2_rn(v.x, v.y);
    __half2 b = __floats2half2_rn(v.z, v.w);
    ((uint2*)dst)[i4] = make_uint2(*(uint32_t*)&a, *(uint32_t*)&b);
}

// ---------------- prep: fp32 -> split fp16 chunk layout --------------------
__global__ void split_chunks(const float* __restrict__ src,
                             unsigned char* __restrict__ dst, int n4) {
    int i4 = blockIdx.x * blockDim.x + threadIdx.x;
    if (i4 >= n4) return;
    const int i = i4 * 4;
    float4 v = ((const float4*)src)[i4];
    uint32_t h0, l0, h1, l1;
    split2h(v.x, v.y, h0, l0);
    split2h(v.z, v.w, h1, l1);
    unsigned char* base = dst + (size_t)(i >> 5) * 128 + (i & 31) * 2;
    *(uint2*)base        = make_uint2(h0, h1);
    *(uint2*)(base + 64) = make_uint2(l0, l1);
}

// ---------------- GEMM1: act = silu(X*W1g+b) * (X*W1l+b) -------------------
// CTA: M=128, Ngate=64, Nlin=64, k-chunk=32. (Ah+Al)xBh exact A, fp16 B.
#define G1_BOFF (128 * ROW_A)              // 18432
#define G1_STG  (G1_BOFF + 128 * ROW_B)    // 28672 per stage

__global__ __launch_bounds__(256, 1)
void gemm1_kernel(const float* __restrict__ b1) {
    const int e   = blockIdx.y;
    const int cnt = g_count[e];
    const int m0  = blockIdx.z * 128;
    if (m0 >= cnt) return;
    const int n0  = blockIdx.x * 64;
    const int off = g_offset[e];

    extern __shared__ char sm[];
    __shared__ float s_bg[64], s_bl[64];

    const int tid = threadIdx.x, lane = tid & 31, wid = tid >> 5;
    const int wm = wid & 1, wn = wid >> 1;

    if (tid < 64)       s_bg[tid]      = b1[(size_t)e * 2 * FF + n0 + tid];
    else if (tid < 128) s_bl[tid - 64] = b1[(size_t)e * 2 * FF + FF + n0 + tid - 64];

    // A staging: 128 rows x 128B; 2 thr/row x 64B
    const int arow = tid >> 1, ahalf = (tid & 1) * 64;
    const int mrow = m0 + arow;
    const int slot = off + (mrow < cnt ? mrow : cnt - 1);
    const unsigned char* srcA = g_hs + (size_t)g_tok[slot] * (H * 4) + ahalf;
    const uint32_t dAo = (uint32_t)arow * ROW_A + ahalf;

    // B staging: 128 rows (64 gate + 64 lin) x 64B; 2 thr/row x 32B
    const int brow = tid >> 1, bhalf = (tid & 1) * 32;
    const int bchan = (brow < 64) ? (e * 2 * FF + n0 + brow)
                                  : (e * 2 * FF + FF + n0 + (brow - 64));
    const unsigned char* srcB = (const unsigned char*)(g_w1h + (size_t)bchan * H) + bhalf;
    const uint32_t dBo = G1_BOFF + (uint32_t)brow * ROW_B + bhalf;

    // ldmatrix bases
    const uint32_t smb = s2u(sm);
    const uint32_t laA = (uint32_t)((lane & 15) + wm * 64) * ROW_A + (lane >> 4) * 16;
    const uint32_t lbB = G1_BOFF + (uint32_t)(wn * 16 + (lane & 7)) * ROW_B +
                         ((lane >> 3) & 1) * 16;

    float cg[4][2][4] = {}, cl[4][2][4] = {};
    uint4 ra[4], rb[2];

#pragma unroll
    for (int q = 0; q < 4; q++) ra[q] = *(const uint4*)(srcA + q * 16);
#pragma unroll
    for (int q = 0; q < 2; q++) rb[q] = *(const uint4*)(srcB + q * 16);

    for (int kt = 0; kt < NK1; kt++) {
        char* bb = sm + (kt & 1) * G1_STG;
#pragma unroll
        for (int q = 0; q < 4; q++) *(uint4*)(bb + dAo + q * 16) = ra[q];
#pragma unroll
        for (int q = 0; q < 2; q++) *(uint4*)(bb + dBo + q * 16) = rb[q];
        __syncthreads();

        if (kt + 1 < NK1) {
            const unsigned char* sa = srcA + (kt + 1) * 128;
            const unsigned char* sb = srcB + (kt + 1) * 64;
#pragma unroll
            for (int q = 0; q < 4; q++) ra[q] = *(const uint4*)(sa + q * 16);
#pragma unroll
            for (int q = 0; q < 2; q++) rb[q] = *(const uint4*)(sb + q * 16);
        }

        const uint32_t bbu = smb + (kt & 1) * G1_STG;
#pragma unroll
        for (int kk = 0; kk < 2; kk++) {
            uint32_t ah[4][4], al[4][4];
#pragma unroll
            for (int i = 0; i < 4; i++) {
                const uint32_t a0 = bbu + laA + i * (16 * ROW_A) + kk * 32;
                ldsm4(ah[i], a0);
                ldsm4(al[i], a0 + 64);
            }
#pragma unroll
            for (int j = 0; j < 2; j++) {
                const uint32_t ba = bbu + lbB + j * (8 * ROW_B) + kk * 32;
                uint32_t bg[2], blin[2];
                ldsm2(bg, ba);
                ldsm2(blin, ba + 64 * ROW_B);
#pragma unroll
                for (int i = 0; i < 4; i++) {
                    mma16816(cg[i][j], ah[i], bg);
                    mma16816(cg[i][j], al[i], bg);
                    mma16816(cl[i][j], ah[i], blin);
                    mma16816(cl[i][j], al[i], blin);
                }
            }
        }
        __syncthreads();
    }

    // epilogue: bias + silu(gate)*lin; store act as split fp16 chunks
#pragma unroll
    for (int i = 0; i < 4; i++)
#pragma unroll
        for (int rr = 0; rr < 2; rr++) {
            const int m = wm * 64 + i * 16 + (lane >> 2) + rr * 8 + m0;
            if (m >= cnt) continue;
            unsigned char* actrow = g_acts + (size_t)(off + m) * (FF * 4);
#pragma unroll
            for (int j = 0; j < 2; j++) {
                const int c = wn * 16 + j * 8 + (lane & 3) * 2;
                float r0, r1;
#pragma unroll
                for (int q = 0; q < 2; q++) {
                    const int idx = rr * 2 + q;
                    const float g = cg[i][j][idx] + s_bg[c + q];
                    const float l = cl[i][j][idx] + s_bl[c + q];
                    const float r = g * l / (1.0f + __expf(-g));
                    if (q == 0) r0 = r; else r1 = r;
                }
                uint32_t h, lo;
                split2h(r0, r1, h, lo);
                const int C = n0 + c;
                unsigned char* base = actrow + (size_t)(C >> 5) * 128 + (C & 31) * 2;
                *(uint32_t*)base        = h;
                *(uint32_t*)(base + 64) = lo;
            }
        }
}

// ---------------- GEMM2: out += scale*(act*W2^T + b2) ----------------------
// CTA: M=128, N=64 over H, K=FF. (Ah+Al)xBh.
#define G2_BOFF (128 * ROW_A)              // 18432
#define G2_STG  (G2_BOFF + 64 * ROW_B)     // 23552 per stage

__global__ __launch_bounds__(256, 1)
void gemm2_kernel(const float* __restrict__ b2, float* __restrict__ out) {
    const int e   = blockIdx.y;
    const int cnt = g_count[e];
    const int m0  = blockIdx.z * 128;
    if (m0 >= cnt) return;
    const int n0  = blockIdx.x * 64;
    const int off = g_offset[e];

    extern __shared__ char sm[];
    __shared__ float s_b2[64];

    const int tid = threadIdx.x, lane = tid & 31, wid = tid >> 5;
    const int wm = wid & 1, wn = wid >> 1;

    if (tid < 64) s_b2[tid] = b2[(size_t)e * H + n0 + tid];

    // A staging: 128 rows x 128B; 2 thr/row x 64B
    const int arow = tid >> 1, ahalf = (tid & 1) * 64;
    const int mrow = m0 + arow;
    const unsigned char* srcA =
        g_acts + (size_t)(off + (mrow < cnt ? mrow : cnt - 1)) * (FF * 4) + ahalf;
    const uint32_t dAo = (uint32_t)arow * ROW_A + ahalf;

    // B staging: 64 rows x 64B; 4 thr/row x 16B
    const int brow = tid >> 2, boff16 = (tid & 3) * 16;
    const unsigned char* srcB =
        (const unsigned char*)(g_w2h + (size_t)(e * H + n0 + brow) * FF) + boff16;
    const uint32_t dBo = G2_BOFF + (uint32_t)brow * ROW_B + boff16;

    const uint32_t smb = s2u(sm);
    const uint32_t laA = (uint32_t)((lane & 15) + wm * 64) * ROW_A + (lane >> 4) * 16;
    const uint32_t lbB = G2_BOFF + (uint32_t)(wn * 16 + (lane & 7)) * ROW_B +
                         ((lane >> 3) & 1) * 16;

    float c[4][2][4] = {};
    uint4 ra[4], rb;

#pragma unroll
    for (int q = 0; q < 4; q++) ra[q] = *(const uint4*)(srcA + q * 16);
    rb = *(const uint4*)srcB;

    for (int kt = 0; kt < NK2; kt++) {
        char* bb = sm + (kt & 1) * G2_STG;
#pragma unroll
        for (int q = 0; q < 4; q++) *(uint4*)(bb + dAo + q * 16) = ra[q];
        *(uint4*)(bb + dBo) = rb;
        __syncthreads();

        if (kt + 1 < NK2) {
            const unsigned char* sa = srcA + (kt + 1) * 128;
            const unsigned char* sb = srcB + (kt + 1) * 64;
#pragma unroll
            for (int q = 0; q < 4; q++) ra[q] = *(const uint4*)(sa + q * 16);
            rb = *(const uint4*)sb;
        }

        const uint32_t bbu = smb + (kt & 1) * G2_STG;
#pragma unroll
        for (int kk = 0; kk < 2; kk++) {
            uint32_t ah[4][4], al[4][4];
#pragma unroll
            for (int i = 0; i < 4; i++) {
                const uint32_t a0 = bbu + laA + i * (16 * ROW_A) + kk * 32;
                ldsm4(ah[i], a0);
                ldsm4(al[i], a0 + 64);
            }
#pragma unroll
            for (int j = 0; j < 2; j++) {
                const uint32_t ba = bbu + lbB + j * (8 * ROW_B) + kk * 32;
                uint32_t bh[2];
                ldsm2(bh, ba);
#pragma unroll
                for (int i = 0; i < 4; i++) {
                    mma16816(c[i][j], ah[i], bh);
                    mma16816(c[i][j], al[i], bh);
                }
            }
        }
        __syncthreads();
    }

    // epilogue: scaled atomic scatter
#pragma unroll
    for (int i = 0; i < 4; i++)
#pragma unroll
        for (int rr = 0; rr < 2; rr++) {
            const int m = wm * 64 + i * 16 + (lane >> 2) + rr * 8 + m0;
            if (m >= cnt) continue;
            const int   sl  = off + m;
            const int   tok = g_tok[sl];
            const float sc  = g_scale[sl];
#pragma unroll
            for (int j = 0; j < 2; j++) {
                const int cc = wn * 16 + j * 8 + (lane & 3) * 2;
                atomicAdd(&out[(size_t)tok * H + n0 + cc],
                          sc * (c[i][j][rr * 2 + 0] + s_b2[cc]));
                atomicAdd(&out[(size_t)tok * H + n0 + cc + 1],
                          sc * (c[i][j][rr * 2 + 1] + s_b2[cc + 1]));
            }
        }
}

// ---------------- launch ----------------
extern "C" void kernel_launch(void* const* d_in, const int* in_sizes, int n_in,
                              void* d_out, int out_size) {
    const float* hidden = (const float*)d_in[0];
    const int*   sel    = (const int*)d_in[1];
    const float* scales = (const float*)d_in[2];
    const float* w1     = (const float*)d_in[3];
    const float* b1     = (const float*)d_in[4];
    const float* w2     = (const float*)d_in[5];
    const float* b2     = (const float*)d_in[6];

    void *p_hs, *p_w1h, *p_w2h;
    cudaGetSymbolAddress(&p_hs,  g_hs);
    cudaGetSymbolAddress(&p_w1h, g_w1h);
    cudaGetSymbolAddress(&p_w2h, g_w2h);

    const int smem1 = 2 * G1_STG;   // 57344
    const int smem2 = 2 * G2_STG;   // 47104
    cudaFuncSetAttribute(gemm1_kernel, cudaFuncAttributeMaxDynamicSharedMemorySize, smem1);
    cudaFuncSetAttribute(gemm2_kernel, cudaFuncAttributeMaxDynamicSharedMemorySize, smem2);

    cudaMemsetAsync(d_out, 0, (size_t)T * H * sizeof(float), 0);
    route_kernel<<<1, 256>>>(sel, scales);

    const int n4h  = (T * H) / 4;
    const int n4w1 = (E * 2 * FF * H) / 4;
    const int n4w2 = (E * H * FF) / 4;
    split_chunks<<<(n4h + 255) / 256, 256>>>(hidden, (unsigned char*)p_hs, n4h);
    tofp16<<<(n4w1 + 255) / 256, 256>>>(w1, (__half*)p_w1h, n4w1);
    tofp16<<<(n4w2 + 255) / 256, 256>>>(w2, (__half*)p_w2h, n4w2);

    dim3 g1(FF / 64, E, NSLOT / 128);   // 32 x 8 x 16
    gemm1_kernel<<<g1, 256, smem1>>>(b1);

    dim3 g2(H / 64, E, NSLOT / 128);    // 16 x 8 x 16
    gemm2_kernel<<<g2, 256, smem2>>>(b2, (float*)d_out);
}